// round 1
// baseline (speedup 1.0000x reference)
#include <cuda_runtime.h>
#include <cuda_bf16.h>

#define Gg 4
#define NN 4096
#define NE 65536
#define NBES 8
#define CC 32

// ---- scratch (static __device__, no allocation) ----
__device__ int   d_cnt[Gg * NN];
__device__ int   d_rowstart[Gg * NN];
__device__ int   d_cursor[Gg * NN];
__device__ int   d_perm[Gg * NE];
__device__ float d_h0[Gg * NN * CC];
__device__ float d_h1[Gg * NN * CC];
__device__ float d_gacc[Gg * 6];

// constants
__device__ __forceinline__ float sq(float v) { return v * v; }

#define PI_OVER_RC   0.5235987755982988f   // pi/6
#define SQRT_2_RC    0.5773502691896258f   // sqrt(2/6)
#define SQ3F         1.7320508075688772f
#define SQRT15       3.872983346207417f    // CY2*SQ2
#define CY2_OVER_SQ6 1.1180339887498949f   // CY2/SQ6
#define CY2_OVER_SQ2 1.9364916731037085f   // CY2/SQ2
#define SQ2F         1.4142135623730951f
#define INV_SQ6      0.4082482904638631f
#define INV_SQ2      0.7071067811865475f
#define INV_SQ3      0.5773502691896258f

// K1: zero counters/accumulators; h0 = node_attr @ Wz
__global__ void k_init(const float* __restrict__ na, const float* __restrict__ Wz) {
    int idx = blockIdx.x * blockDim.x + threadIdx.x;
    if (idx < Gg * NN * CC) {
        int node = idx / CC;
        int c = idx & (CC - 1);
        const float* a = na + node * 3;
        d_h0[idx] = a[0] * Wz[c] + a[1] * Wz[CC + c] + a[2] * Wz[2 * CC + c];
    }
    if (idx < Gg * NN) d_cnt[idx] = 0;
    if (idx < Gg * 6) d_gacc[idx] = 0.f;
}

// K2: histogram of destinations
__global__ void k_hist(const int* __restrict__ ei) {
    int idx = blockIdx.x * blockDim.x + threadIdx.x;
    if (idx >= Gg * NE) return;
    int g = idx >> 16;
    int e = idx & (NE - 1);
    int dst = ei[g * 2 * NE + NE + e];
    atomicAdd(&d_cnt[g * NN + dst], 1);
}

// K3: exclusive scan per graph (one block of 1024 threads, 4 elems each)
__global__ void k_scan() {
    int g = blockIdx.x;
    int t = threadIdx.x;
    __shared__ int sm[1024];
    int base = g * NN + t * 4;
    int v0 = d_cnt[base], v1 = d_cnt[base + 1], v2 = d_cnt[base + 2], v3 = d_cnt[base + 3];
    sm[t] = v0 + v1 + v2 + v3;
    __syncthreads();
    for (int off = 1; off < 1024; off <<= 1) {
        int x = (t >= off) ? sm[t - off] : 0;
        __syncthreads();
        sm[t] += x;
        __syncthreads();
    }
    int run = (t > 0) ? sm[t - 1] : 0;
    d_rowstart[base] = run;     d_cursor[base] = run;     run += v0;
    d_rowstart[base + 1] = run; d_cursor[base + 1] = run; run += v1;
    d_rowstart[base + 2] = run; d_cursor[base + 2] = run; run += v2;
    d_rowstart[base + 3] = run; d_cursor[base + 3] = run;
}

// K4: scatter edge ids into CSR order
__global__ void k_scatter(const int* __restrict__ ei) {
    int idx = blockIdx.x * blockDim.x + threadIdx.x;
    if (idx >= Gg * NE) return;
    int g = idx >> 16;
    int e = idx & (NE - 1);
    int dst = ei[g * 2 * NE + NE + e];
    int pos = atomicAdd(&d_cursor[g * NN + dst], 1);
    d_perm[g * NE + pos] = e;
}

// K5/K6: fused message-pass + prod3body + readout (+ f0 update in pass1)
// one warp per node, lane = channel
template <bool PASS1>
__global__ void __launch_bounds__(256, 8)
k_pass(const float* __restrict__ x, const float* __restrict__ xv,
       const int* __restrict__ ei,
       const float* __restrict__ Wrad, const float* __restrict__ Wp,
       const float* __restrict__ Wr0, const float* __restrict__ Wr2,
       const float* __restrict__ Wm0) {
    __shared__ float sWrad[NBES * CC * 3];
    __shared__ float sWm0[CC * CC];
    for (int i = threadIdx.x; i < NBES * CC * 3; i += blockDim.x) sWrad[i] = Wrad[i];
    if (PASS1)
        for (int i = threadIdx.x; i < CC * CC; i += blockDim.x) sWm0[i] = Wm0[i];
    __syncthreads();

    int warp = (blockIdx.x * blockDim.x + threadIdx.x) >> 5;   // exactly Gg*NN warps
    int lane = threadIdx.x & 31;
    int g = warp >> 12;
    int n = warp & (NN - 1);

    const float* hin = PASS1 ? d_h0 : d_h1;

    int start = d_rowstart[g * NN + n];
    int deg = d_cnt[g * NN + n];
    const int gE = g * NE;
    const float* sWc = sWrad + lane * 3;

    float a0 = 0.f, a1x = 0.f, a1y = 0.f, a1z = 0.f;
    float q0 = 0.f, q1 = 0.f, q2 = 0.f, q3 = 0.f, q4 = 0.f;

    for (int i = 0; i < deg; i++) {
        int e = d_perm[gE + start + i];
        float r = x[gE + e];
        const float* v = xv + (gE + e) * 3;
        float vx = v[0], vy = v[1], vz = v[2];
        int src = ei[g * 2 * NE + e];
        float hs = hin[(g * NN + src) * CC + lane];

        // radial Bessel basis: sqrt(2/rc) * sin(n*theta)/r via sin recurrence
        float Rr[8];
        {
            float theta = r * PI_OVER_RC;
            float s1, c1;
            __sincosf(theta, &s1, &c1);
            float tc = c1 + c1;
            float inv = (r > 1e-12f) ? (SQRT_2_RC / r) : 0.f;
            float sm1 = 0.f, sc = s1;
#pragma unroll
            for (int b = 0; b < 8; b++) {
                Rr[b] = sc * inv;
                float nx = tc * sc - sm1;
                sm1 = sc; sc = nx;
            }
            if (r <= 1e-12f) {
#pragma unroll
                for (int b = 0; b < 8; b++) Rr[b] = SQRT_2_RC * (b + 1) * PI_OVER_RC;
            }
        }

        // spherical harmonics of unit edge vector
        float nv = sqrtf(vx * vx + vy * vy + vz * vz);
        float inu = 1.f / (nv + 1e-9f);
        float ux = vx * inu, uy = vy * inu, uz = vz * inu;
        float Y1x = SQ3F * ux, Y1y = SQ3F * uy, Y1z = SQ3F * uz;
        float ux2 = ux * ux, uy2 = uy * uy, uz2 = uz * uz;
        float Y2a = SQRT15 * ux * uy;
        float Y2b = SQRT15 * uy * uz;
        float Y2c = CY2_OVER_SQ6 * (2.f * uz2 - ux2 - uy2);
        float Y2d = SQRT15 * ux * uz;
        float Y2e = CY2_OVER_SQ2 * (ux2 - uy2);

        // radial weights per channel
        float w0 = 0.f, w1 = 0.f, w2 = 0.f;
#pragma unroll
        for (int b = 0; b < 8; b++) {
            float rb = Rr[b];
            w0 += rb * sWc[b * 96 + 0];
            w1 += rb * sWc[b * 96 + 1];
            w2 += rb * sWc[b * 96 + 2];
        }
        float g0 = w0 * hs, g1 = w1 * hs, g2 = w2 * hs;
        a0 += g0;
        a1x += g1 * Y1x; a1y += g1 * Y1y; a1z += g1 * Y1z;
        q0 += g2 * Y2a; q1 += g2 * Y2b; q2 += g2 * Y2c; q3 += g2 * Y2d; q4 += g2 * Y2e;
    }

    // ---- prod3body (paths 0 and 2 only; path 1 is never consumed) ----
    float d11 = a1x * a1x + a1y * a1y + a1z * a1z;
    float d22 = q0 * q0 + q1 * q1 + q2 * q2 + q3 * q3 + q4 * q4;
    float B0 = Wp[lane] * a0 * a0 + Wp[CC + lane] * d11 + Wp[2 * CC + lane] * d22;

    float t5a = SQ2F * a1x * a1y;
    float t5b = SQ2F * a1y * a1z;
    float t5c = (2.f * a1z * a1z - a1x * a1x - a1y * a1y) * INV_SQ6;
    float t5d = SQ2F * a1x * a1z;
    float t5e = (a1x * a1x - a1y * a1y) * INV_SQ2;
    float w5 = Wp[5 * CC + lane], w6 = Wp[6 * CC + lane];
    float B2a = w5 * a0 * q0 + w6 * t5a;
    float B2b = w5 * a0 * q1 + w6 * t5b;
    float B2c = w5 * a0 * q2 + w6 * t5c;
    float B2d = w5 * a0 * q3 + w6 * t5d;
    float B2e = w5 * a0 * q4 + w6 * t5e;

    // ---- readout partials ----
    float wr0 = Wr0[lane], wr2 = Wr2[lane];
    float sv = B0 * wr0;
    float t0v = B2a * wr2, t1v = B2b * wr2, t2v = B2c * wr2;
    float t3v = B2d * wr2, t4v = B2e * wr2;
#pragma unroll
    for (int off = 16; off; off >>= 1) {
        sv  += __shfl_xor_sync(0xffffffffu, sv, off);
        t0v += __shfl_xor_sync(0xffffffffu, t0v, off);
        t1v += __shfl_xor_sync(0xffffffffu, t1v, off);
        t2v += __shfl_xor_sync(0xffffffffu, t2v, off);
        t3v += __shfl_xor_sync(0xffffffffu, t3v, off);
        t4v += __shfl_xor_sync(0xffffffffu, t4v, off);
    }
    if (lane == 0) {
        atomicAdd(&d_gacc[g * 6 + 0], sv);
        atomicAdd(&d_gacc[g * 6 + 1], t0v);
        atomicAdd(&d_gacc[g * 6 + 2], t1v);
        atomicAdd(&d_gacc[g * 6 + 3], t2v);
        atomicAdd(&d_gacc[g * 6 + 4], t3v);
        atomicAdd(&d_gacc[g * 6 + 5], t4v);
    }

    // ---- node scalar update (pass1 only): f0 = silu(B0 @ Wm0) ----
    if (PASS1) {
        float f = 0.f;
#pragma unroll
        for (int k = 0; k < 32; k++) {
            float bk = __shfl_sync(0xffffffffu, B0, k);
            f += bk * sWm0[k * CC + lane];
        }
        f = f / (1.f + __expf(-f));
        d_h1[(g * NN + n) * CC + lane] = f;
    }
}

// K7: finalize -> out[g] = s/sqrt3 * I + mat_from_t5(t)
__global__ void k_finalize(float* __restrict__ out) {
    int g = threadIdx.x;
    if (g >= Gg) return;
    float s = d_gacc[g * 6 + 0];
    float a = d_gacc[g * 6 + 1];
    float b = d_gacc[g * 6 + 2];
    float c = d_gacc[g * 6 + 3];
    float d = d_gacc[g * 6 + 4];
    float e = d_gacc[g * 6 + 5];
    float diag = s * INV_SQ3;
    out[g * 9 + 0] = diag - c * INV_SQ6 + e * INV_SQ2;
    out[g * 9 + 1] = a * INV_SQ2;
    out[g * 9 + 2] = d * INV_SQ2;
    out[g * 9 + 3] = a * INV_SQ2;
    out[g * 9 + 4] = diag - c * INV_SQ6 - e * INV_SQ2;
    out[g * 9 + 5] = b * INV_SQ2;
    out[g * 9 + 6] = d * INV_SQ2;
    out[g * 9 + 7] = b * INV_SQ2;
    out[g * 9 + 8] = diag + 2.f * c * INV_SQ6;
}

extern "C" void kernel_launch(void* const* d_in, const int* in_sizes, int n_in,
                              void* d_out, int out_size) {
    const float* x     = (const float*)d_in[0];
    const float* xv    = (const float*)d_in[1];
    const float* na    = (const float*)d_in[2];
    const int*   ei    = (const int*)d_in[3];
    const float* Wz    = (const float*)d_in[4];
    const float* Wrad1 = (const float*)d_in[5];
    const float* Wrad2 = (const float*)d_in[6];
    const float* Wp    = (const float*)d_in[7];
    const float* Wr0_1 = (const float*)d_in[8];
    const float* Wr2_1 = (const float*)d_in[9];
    const float* Wm0   = (const float*)d_in[10];
    const float* Wr0_2 = (const float*)d_in[11];
    const float* Wr2_2 = (const float*)d_in[12];
    float* out = (float*)d_out;

    k_init<<<(Gg * NN * CC + 255) / 256, 256>>>(na, Wz);
    k_hist<<<(Gg * NE + 255) / 256, 256>>>(ei);
    k_scan<<<Gg, 1024>>>();
    k_scatter<<<(Gg * NE + 255) / 256, 256>>>(ei);
    k_pass<true><<<(Gg * NN * 32) / 256, 256>>>(x, xv, ei, Wrad1, Wp, Wr0_1, Wr2_1, Wm0);
    k_pass<false><<<(Gg * NN * 32) / 256, 256>>>(x, xv, ei, Wrad2, Wp, Wr0_2, Wr2_2, Wm0);
    k_finalize<<<1, 32>>>(out);
}

// round 2
// speedup vs baseline: 1.0789x; 1.0789x over previous
#include <cuda_runtime.h>
#include <cuda_bf16.h>

#define Gg 4
#define NN 4096
#define NE 65536
#define NBES 8
#define CC 32

// ---- scratch (static __device__, no allocation) ----
__device__ int   d_cnt[Gg * NN];
__device__ int   d_rowstart[Gg * NN];
__device__ int   d_cursor[Gg * NN];
__device__ int   d_src[Gg * NE];            // src node id, CSR order
__device__ float d_geom[Gg * NE * 16];      // per-edge record (CSR order): R[8], Y1[3], Y2[5]
__device__ float d_h0[Gg * NN * CC];
__device__ float d_h1[Gg * NN * CC];
__device__ float d_gacc[Gg * 6];

#define PI_OVER_RC   0.5235987755982988f   // pi/6
#define SQRT_2_RC    0.5773502691896258f   // sqrt(2/6)
#define SQ3F         1.7320508075688772f
#define SQRT15       3.872983346207417f    // CY2*SQ2
#define CY2_OVER_SQ6 1.1180339887498949f   // CY2/SQ6
#define CY2_OVER_SQ2 1.9364916731037085f   // CY2/SQ2
#define SQ2F         1.4142135623730951f
#define INV_SQ6      0.4082482904638631f
#define INV_SQ2      0.7071067811865475f
#define INV_SQ3      0.5773502691896258f

// K1: zero counters/accumulators; h0 = node_attr @ Wz
__global__ void k_init(const float* __restrict__ na, const float* __restrict__ Wz) {
    int idx = blockIdx.x * blockDim.x + threadIdx.x;
    if (idx < Gg * NN * CC) {
        int node = idx / CC;
        int c = idx & (CC - 1);
        const float* a = na + node * 3;
        d_h0[idx] = a[0] * Wz[c] + a[1] * Wz[CC + c] + a[2] * Wz[2 * CC + c];
    }
    if (idx < Gg * NN) d_cnt[idx] = 0;
    if (idx < Gg * 6) d_gacc[idx] = 0.f;
}

// K2: histogram of destinations
__global__ void k_hist(const int* __restrict__ ei) {
    int idx = blockIdx.x * blockDim.x + threadIdx.x;
    if (idx >= Gg * NE) return;
    int g = idx >> 16;
    int e = idx & (NE - 1);
    int dst = ei[g * 2 * NE + NE + e];
    atomicAdd(&d_cnt[g * NN + dst], 1);
}

// K3: exclusive scan per graph (one block of 1024 threads, 4 elems each)
__global__ void k_scan() {
    int g = blockIdx.x;
    int t = threadIdx.x;
    __shared__ int sm[1024];
    int base = g * NN + t * 4;
    int v0 = d_cnt[base], v1 = d_cnt[base + 1], v2 = d_cnt[base + 2], v3 = d_cnt[base + 3];
    sm[t] = v0 + v1 + v2 + v3;
    __syncthreads();
    for (int off = 1; off < 1024; off <<= 1) {
        int x = (t >= off) ? sm[t - off] : 0;
        __syncthreads();
        sm[t] += x;
        __syncthreads();
    }
    int run = (t > 0) ? sm[t - 1] : 0;
    d_rowstart[base] = run;     d_cursor[base] = run;     run += v0;
    d_rowstart[base + 1] = run; d_cursor[base + 1] = run; run += v1;
    d_rowstart[base + 2] = run; d_cursor[base + 2] = run; run += v2;
    d_rowstart[base + 3] = run; d_cursor[base + 3] = run;
}

// K4: scatter + per-edge geometry (computed ONCE, shared by both passes).
// Record (16 floats, 64B aligned): R[8], Y1x,Y1y,Y1z, Y2a..Y2e (premultiplied norms).
__global__ void k_scatter_geom(const int* __restrict__ ei,
                               const float* __restrict__ x,
                               const float* __restrict__ xv) {
    int idx = blockIdx.x * blockDim.x + threadIdx.x;
    if (idx >= Gg * NE) return;
    int g = idx >> 16;
    int e = idx & (NE - 1);
    int dst = ei[g * 2 * NE + NE + e];
    int src = ei[g * 2 * NE + e];
    int pos = atomicAdd(&d_cursor[g * NN + dst], 1);
    d_src[g * NE + pos] = src;

    float r = x[g * NE + e];
    const float* v = xv + (g * NE + e) * 3;
    float vx = v[0], vy = v[1], vz = v[2];

    // radial Bessel basis via sin recurrence
    float Rr[8];
    {
        float theta = r * PI_OVER_RC;
        float s1, c1;
        __sincosf(theta, &s1, &c1);
        float tc = c1 + c1;
        float inv = (r > 1e-12f) ? (SQRT_2_RC / r) : 0.f;
        float sm1 = 0.f, sc = s1;
#pragma unroll
        for (int b = 0; b < 8; b++) {
            Rr[b] = sc * inv;
            float nx = tc * sc - sm1;
            sm1 = sc; sc = nx;
        }
        if (r <= 1e-12f) {
#pragma unroll
            for (int b = 0; b < 8; b++) Rr[b] = SQRT_2_RC * (b + 1) * PI_OVER_RC;
        }
    }

    // spherical harmonics of the unit edge vector (premultiplied norms)
    float nv = sqrtf(vx * vx + vy * vy + vz * vz);
    float inu = 1.f / (nv + 1e-9f);
    float ux = vx * inu, uy = vy * inu, uz = vz * inu;
    float ux2 = ux * ux, uy2 = uy * uy, uz2 = uz * uz;

    float4* rec = reinterpret_cast<float4*>(d_geom) + (size_t)(g * NE + pos) * 4;
    rec[0] = make_float4(Rr[0], Rr[1], Rr[2], Rr[3]);
    rec[1] = make_float4(Rr[4], Rr[5], Rr[6], Rr[7]);
    rec[2] = make_float4(SQ3F * ux, SQ3F * uy, SQ3F * uz, SQRT15 * ux * uy);
    rec[3] = make_float4(SQRT15 * uy * uz,
                         CY2_OVER_SQ6 * (2.f * uz2 - ux2 - uy2),
                         SQRT15 * ux * uz,
                         CY2_OVER_SQ2 * (ux2 - uy2));
}

// K5/K6: fused message-pass + prod3body + readout (+ f0 update in pass1)
// one warp per node, lane = channel. Streaming CSR geometry, W in registers.
template <bool PASS1>
__global__ void __launch_bounds__(256, 3)
k_pass(const float* __restrict__ Wrad, const float* __restrict__ Wp,
       const float* __restrict__ Wr0, const float* __restrict__ Wr2,
       const float* __restrict__ Wm0) {
    __shared__ float sWm0[CC * CC];
    if (PASS1) {
        for (int i = threadIdx.x; i < CC * CC; i += blockDim.x) sWm0[i] = Wm0[i];
        __syncthreads();
    }

    int warp = (blockIdx.x * blockDim.x + threadIdx.x) >> 5;   // exactly Gg*NN warps
    int lane = threadIdx.x & 31;
    int g = warp >> 12;
    int n = warp & (NN - 1);

    // per-lane radial weights in registers: wr[b][l]
    float wr[NBES][3];
#pragma unroll
    for (int b = 0; b < NBES; b++) {
        wr[b][0] = Wrad[b * 96 + lane * 3 + 0];
        wr[b][1] = Wrad[b * 96 + lane * 3 + 1];
        wr[b][2] = Wrad[b * 96 + lane * 3 + 2];
    }

    const float* hin = PASS1 ? d_h0 : d_h1;
    const float* hbase = hin + g * NN * CC + lane;

    int start = d_rowstart[g * NN + n];
    int deg = d_cnt[g * NN + n];
    int p = g * NE + start;

    float a0 = 0.f, a1x = 0.f, a1y = 0.f, a1z = 0.f;
    float q0 = 0.f, q1 = 0.f, q2 = 0.f, q3 = 0.f, q4 = 0.f;

#pragma unroll 2
    for (int i = 0; i < deg; i++) {
        const float4* rec = reinterpret_cast<const float4*>(d_geom) + (size_t)(p + i) * 4;
        float4 Ra = rec[0];
        float4 Rb = rec[1];
        float4 Ya = rec[2];
        float4 Yb = rec[3];
        int src = d_src[p + i];
        float hs = hbase[src * CC];

        float w0 = Ra.x * wr[0][0] + Ra.y * wr[1][0] + Ra.z * wr[2][0] + Ra.w * wr[3][0]
                 + Rb.x * wr[4][0] + Rb.y * wr[5][0] + Rb.z * wr[6][0] + Rb.w * wr[7][0];
        float w1 = Ra.x * wr[0][1] + Ra.y * wr[1][1] + Ra.z * wr[2][1] + Ra.w * wr[3][1]
                 + Rb.x * wr[4][1] + Rb.y * wr[5][1] + Rb.z * wr[6][1] + Rb.w * wr[7][1];
        float w2 = Ra.x * wr[0][2] + Ra.y * wr[1][2] + Ra.z * wr[2][2] + Ra.w * wr[3][2]
                 + Rb.x * wr[4][2] + Rb.y * wr[5][2] + Rb.z * wr[6][2] + Rb.w * wr[7][2];

        float g0 = w0 * hs, g1 = w1 * hs, g2 = w2 * hs;
        a0 += g0;
        a1x += g1 * Ya.x; a1y += g1 * Ya.y; a1z += g1 * Ya.z;
        q0 += g2 * Ya.w;  q1 += g2 * Yb.x;  q2 += g2 * Yb.y;
        q3 += g2 * Yb.z;  q4 += g2 * Yb.w;
    }

    // ---- prod3body (paths 0 and 2; path 1 never consumed by readout) ----
    float d11 = a1x * a1x + a1y * a1y + a1z * a1z;
    float d22 = q0 * q0 + q1 * q1 + q2 * q2 + q3 * q3 + q4 * q4;
    float B0 = Wp[lane] * a0 * a0 + Wp[CC + lane] * d11 + Wp[2 * CC + lane] * d22;

    float t5a = SQ2F * a1x * a1y;
    float t5b = SQ2F * a1y * a1z;
    float t5c = (2.f * a1z * a1z - a1x * a1x - a1y * a1y) * INV_SQ6;
    float t5d = SQ2F * a1x * a1z;
    float t5e = (a1x * a1x - a1y * a1y) * INV_SQ2;
    float w5 = Wp[5 * CC + lane], w6 = Wp[6 * CC + lane];
    float B2a = w5 * a0 * q0 + w6 * t5a;
    float B2b = w5 * a0 * q1 + w6 * t5b;
    float B2c = w5 * a0 * q2 + w6 * t5c;
    float B2d = w5 * a0 * q3 + w6 * t5d;
    float B2e = w5 * a0 * q4 + w6 * t5e;

    // ---- readout partials ----
    float wr0 = Wr0[lane], wr2 = Wr2[lane];
    float sv = B0 * wr0;
    float t0v = B2a * wr2, t1v = B2b * wr2, t2v = B2c * wr2;
    float t3v = B2d * wr2, t4v = B2e * wr2;
#pragma unroll
    for (int off = 16; off; off >>= 1) {
        sv  += __shfl_xor_sync(0xffffffffu, sv, off);
        t0v += __shfl_xor_sync(0xffffffffu, t0v, off);
        t1v += __shfl_xor_sync(0xffffffffu, t1v, off);
        t2v += __shfl_xor_sync(0xffffffffu, t2v, off);
        t3v += __shfl_xor_sync(0xffffffffu, t3v, off);
        t4v += __shfl_xor_sync(0xffffffffu, t4v, off);
    }
    if (lane == 0) {
        atomicAdd(&d_gacc[g * 6 + 0], sv);
        atomicAdd(&d_gacc[g * 6 + 1], t0v);
        atomicAdd(&d_gacc[g * 6 + 2], t1v);
        atomicAdd(&d_gacc[g * 6 + 3], t2v);
        atomicAdd(&d_gacc[g * 6 + 4], t3v);
        atomicAdd(&d_gacc[g * 6 + 5], t4v);
    }

    // ---- node scalar update (pass1 only): f0 = silu(B0 @ Wm0) ----
    if (PASS1) {
        float f = 0.f;
#pragma unroll
        for (int k = 0; k < 32; k++) {
            float bk = __shfl_sync(0xffffffffu, B0, k);
            f += bk * sWm0[k * CC + lane];
        }
        f = f / (1.f + __expf(-f));
        d_h1[(g * NN + n) * CC + lane] = f;
    }
}

// K7: finalize -> out[g] = s/sqrt3 * I + mat_from_t5(t)
__global__ void k_finalize(float* __restrict__ out) {
    int g = threadIdx.x;
    if (g >= Gg) return;
    float s = d_gacc[g * 6 + 0];
    float a = d_gacc[g * 6 + 1];
    float b = d_gacc[g * 6 + 2];
    float c = d_gacc[g * 6 + 3];
    float d = d_gacc[g * 6 + 4];
    float e = d_gacc[g * 6 + 5];
    float diag = s * INV_SQ3;
    out[g * 9 + 0] = diag - c * INV_SQ6 + e * INV_SQ2;
    out[g * 9 + 1] = a * INV_SQ2;
    out[g * 9 + 2] = d * INV_SQ2;
    out[g * 9 + 3] = a * INV_SQ2;
    out[g * 9 + 4] = diag - c * INV_SQ6 - e * INV_SQ2;
    out[g * 9 + 5] = b * INV_SQ2;
    out[g * 9 + 6] = d * INV_SQ2;
    out[g * 9 + 7] = b * INV_SQ2;
    out[g * 9 + 8] = diag + 2.f * c * INV_SQ6;
}

extern "C" void kernel_launch(void* const* d_in, const int* in_sizes, int n_in,
                              void* d_out, int out_size) {
    const float* x     = (const float*)d_in[0];
    const float* xv    = (const float*)d_in[1];
    const float* na    = (const float*)d_in[2];
    const int*   ei    = (const int*)d_in[3];
    const float* Wz    = (const float*)d_in[4];
    const float* Wrad1 = (const float*)d_in[5];
    const float* Wrad2 = (const float*)d_in[6];
    const float* Wp    = (const float*)d_in[7];
    const float* Wr0_1 = (const float*)d_in[8];
    const float* Wr2_1 = (const float*)d_in[9];
    const float* Wm0   = (const float*)d_in[10];
    const float* Wr0_2 = (const float*)d_in[11];
    const float* Wr2_2 = (const float*)d_in[12];
    float* out = (float*)d_out;

    k_init<<<(Gg * NN * CC + 255) / 256, 256>>>(na, Wz);
    k_hist<<<(Gg * NE + 255) / 256, 256>>>(ei);
    k_scan<<<Gg, 1024>>>();
    k_scatter_geom<<<(Gg * NE + 255) / 256, 256>>>(ei, x, xv);
    k_pass<true><<<(Gg * NN * 32) / 256, 256>>>(Wrad1, Wp, Wr0_1, Wr2_1, Wm0);
    k_pass<false><<<(Gg * NN * 32) / 256, 256>>>(Wrad2, Wp, Wr0_2, Wr2_2, Wm0);
    k_finalize<<<1, 32>>>(out);
}